// round 12
// baseline (speedup 1.0000x reference)
#include <cuda_runtime.h>

// Problem constants (fixed by the reference: x,y are [8192, 1024] fp32)
#define N_ROWS 8192
#define D      1024
#define WARPS_PER_BLOCK 8
#define GRID 1184                      // 148 SMs * 8 CTAs/SM: exactly fills
                                       // the 32-reg occupancy limit, 1 wave
#define BLOCK_THREADS (WARPS_PER_BLOCK * 32)   // 256

__device__ float g_partials[GRID];
__device__ unsigned int g_counter = 0;

// Roofline note (R1-R11): LDG.128, 1 row/warp, 256-thread blocks, 32 regs is
// the proven shape (~6.0 TB/s timed). Occupancy limit is 8 CTAs/SM; R2's 1024
// blocks gave 84% occ, R11's 512 gave 44% (regressed). This round fills the
// limit exactly (1184 blocks, 100% occ, still single wave). Warps beyond row
// 8191 contribute zero.
__global__ __launch_bounds__(BLOCK_THREADS)
void row_loss_fused_kernel(const float* __restrict__ x,
                           const float* __restrict__ y,
                           float* __restrict__ out) {
    const int warp = threadIdx.x >> 5;
    const int lane = threadIdx.x & 31;
    const int row  = blockIdx.x * WARPS_PER_BLOCK + warp;

    float loss = 0.0f;  // meaningful on lane 0 only

    if (row < N_ROWS) {
        const float4* __restrict__ xr =
            reinterpret_cast<const float4*>(x + (size_t)row * D);
        const float4* __restrict__ yr =
            reinterpret_cast<const float4*>(y + (size_t)row * D);

        float dot = 0.0f, xx = 0.0f, yy = 0.0f;

        // 1024 floats/row = 256 float4. Lane l reads float4 l, l+32, ...
        // -> contiguous 512B warp bursts (proven-best R2 pattern).
        #pragma unroll
        for (int k = 0; k < 8; k++) {
            float4 a = xr[lane + 32 * k];
            float4 b = yr[lane + 32 * k];
            dot += a.x * b.x + a.y * b.y + a.z * b.z + a.w * b.w;
            xx  += a.x * a.x + a.y * a.y + a.z * a.z + a.w * a.w;
            yy  += b.x * b.x + b.y * b.y + b.z * b.z + b.w * b.w;
        }

        #pragma unroll
        for (int off = 16; off > 0; off >>= 1) {
            dot += __shfl_down_sync(0xFFFFFFFFu, dot, off);
            xx  += __shfl_down_sync(0xFFFFFFFFu, xx,  off);
            yy  += __shfl_down_sync(0xFFFFFFFFu, yy,  off);
        }

        if (lane == 0) {
            float inv_norm = rsqrtf(fmaxf(xx * yy, 1e-24f));
            float cosv = dot * inv_norm;
            float arg  = fmaxf((cosv + 1.0f) * 0.5f, 1e-30f);
            loss = -logf(arg);
        }
    }

    __shared__ float s_loss[WARPS_PER_BLOCK];
    if (lane == 0) s_loss[warp] = loss;
    __syncthreads();

    __shared__ bool s_is_last;
    if (threadIdx.x == 0) {
        float t = 0.0f;
        #pragma unroll
        for (int i = 0; i < WARPS_PER_BLOCK; i++) t += s_loss[i];
        g_partials[blockIdx.x] = t;
        __threadfence();
        unsigned int prev = atomicAdd(&g_counter, 1u);
        s_is_last = (prev == (unsigned int)(GRID - 1));
    }
    __syncthreads();

    // Single last-arriving block: deterministic fixed-order reduction of all
    // partials; re-arms the counter for the next graph replay.
    if (s_is_last) {
        float v = 0.0f;
        for (int idx = threadIdx.x; idx < GRID; idx += BLOCK_THREADS)
            v += g_partials[idx];

        #pragma unroll
        for (int off = 16; off > 0; off >>= 1)
            v += __shfl_down_sync(0xFFFFFFFFu, v, off);

        __shared__ float s_fin[WARPS_PER_BLOCK];
        if (lane == 0) s_fin[warp] = v;
        __syncthreads();

        if (threadIdx.x == 0) {
            float t = 0.0f;
            #pragma unroll
            for (int i = 0; i < WARPS_PER_BLOCK; i++) t += s_fin[i];
            out[0] = t * (1.0f / (float)N_ROWS);
            g_counter = 0;  // re-arm for next graph replay
        }
    }
}

extern "C" void kernel_launch(void* const* d_in, const int* in_sizes, int n_in,
                              void* d_out, int out_size) {
    const float* x = (const float*)d_in[0];
    const float* y = (const float*)d_in[1];
    float* out = (float*)d_out;

    row_loss_fused_kernel<<<GRID, BLOCK_THREADS>>>(x, y, out);
}

// round 13
// speedup vs baseline: 1.1471x; 1.1471x over previous
#include <cuda_runtime.h>

// Problem constants (fixed by the reference: x,y are [8192, 1024] fp32)
#define N_ROWS 8192
#define D      1024
#define WARPS_PER_BLOCK 8
#define NUM_BLOCKS (N_ROWS / WARPS_PER_BLOCK)  // 1024
#define BLOCK_THREADS (WARPS_PER_BLOCK * 32)   // 256

// Per-block partial sums of -log((cos+1)/2). Every slot is rewritten on every
// call before being read, so no reset pass is needed.
__device__ float g_partials[NUM_BLOCKS];
// Arrival counter for the last-block-done pattern. Starts at 0 (static init)
// and is reset to 0 by the last block each call -> graph-replay safe.
__device__ unsigned int g_counter = 0;

// FINAL (rounds 1-12): this shape — LDG.128, 1 row/warp, 256-thread blocks,
// 32 regs, grid 1024 — is the measured optimum at ~6.0 TB/s effective, the
// path-independent chip byte/cycle ceiling. Tested and rejected: 256-bit
// loads (R3), 2 warps/row (R4), higher reg budget (R5), L2 evict_last (R7),
// TMA bulk-copy pipelines shallow and deep (R8/R9), half-grid persistent
// (R11), full-occupancy 1184-block grid (R12). All regressed or tied.
__global__ __launch_bounds__(BLOCK_THREADS)
void row_loss_fused_kernel(const float* __restrict__ x,
                           const float* __restrict__ y,
                           float* __restrict__ out) {
    const int warp = threadIdx.x >> 5;
    const int lane = threadIdx.x & 31;
    const int row  = blockIdx.x * WARPS_PER_BLOCK + warp;

    const float4* __restrict__ xr =
        reinterpret_cast<const float4*>(x + (size_t)row * D);
    const float4* __restrict__ yr =
        reinterpret_cast<const float4*>(y + (size_t)row * D);

    float dot = 0.0f, xx = 0.0f, yy = 0.0f;

    // 1024 floats/row = 256 float4. Lane l reads float4 indices l, l+32, ...
    // -> contiguous 512B warp bursts, 16 independent 16B loads per thread.
    #pragma unroll
    for (int k = 0; k < 8; k++) {
        float4 a = xr[lane + 32 * k];
        float4 b = yr[lane + 32 * k];
        dot += a.x * b.x + a.y * b.y + a.z * b.z + a.w * b.w;
        xx  += a.x * a.x + a.y * a.y + a.z * a.z + a.w * a.w;
        yy  += b.x * b.x + b.y * b.y + b.z * b.z + b.w * b.w;
    }

    // Warp tree reduction of the three accumulators.
    #pragma unroll
    for (int off = 16; off > 0; off >>= 1) {
        dot += __shfl_down_sync(0xFFFFFFFFu, dot, off);
        xx  += __shfl_down_sync(0xFFFFFFFFu, xx,  off);
        yy  += __shfl_down_sync(0xFFFFFFFFu, yy,  off);
    }

    __shared__ float s_loss[WARPS_PER_BLOCK];
    if (lane == 0) {
        float inv_norm = rsqrtf(fmaxf(xx * yy, 1e-24f));
        float cosv = dot * inv_norm;
        float arg  = fmaxf((cosv + 1.0f) * 0.5f, 1e-30f);
        s_loss[warp] = -logf(arg);
    }
    __syncthreads();

    __shared__ bool s_is_last;
    if (threadIdx.x == 0) {
        float t = 0.0f;
        #pragma unroll
        for (int i = 0; i < WARPS_PER_BLOCK; i++) t += s_loss[i];
        g_partials[blockIdx.x] = t;
        // Make the partial visible device-wide before signaling arrival.
        __threadfence();
        unsigned int prev = atomicAdd(&g_counter, 1u);
        s_is_last = (prev == (unsigned int)(NUM_BLOCKS - 1));
    }
    __syncthreads();

    // The single last-arriving block reduces all partials (fixed read order
    // -> deterministic result) and resets the counter for the next replay.
    if (s_is_last) {
        float v = 0.0f;
        #pragma unroll
        for (int i = 0; i < NUM_BLOCKS / BLOCK_THREADS; i++)
            v += g_partials[threadIdx.x + i * BLOCK_THREADS];

        #pragma unroll
        for (int off = 16; off > 0; off >>= 1)
            v += __shfl_down_sync(0xFFFFFFFFu, v, off);

        __shared__ float s_fin[WARPS_PER_BLOCK];
        if (lane == 0) s_fin[warp] = v;
        __syncthreads();

        if (threadIdx.x == 0) {
            float t = 0.0f;
            #pragma unroll
            for (int i = 0; i < WARPS_PER_BLOCK; i++) t += s_fin[i];
            out[0] = t * (1.0f / (float)N_ROWS);
            g_counter = 0;  // re-arm for next graph replay
        }
    }
}

extern "C" void kernel_launch(void* const* d_in, const int* in_sizes, int n_in,
                              void* d_out, int out_size) {
    const float* x = (const float*)d_in[0];
    const float* y = (const float*)d_in[1];
    float* out = (float*)d_out;

    row_loss_fused_kernel<<<NUM_BLOCKS, BLOCK_THREADS>>>(x, y, out);
}

// round 14
// speedup vs baseline: 1.1782x; 1.0272x over previous
#include <cuda_runtime.h>

// Problem constants (fixed by the reference: x,y are [8192, 1024] fp32)
#define N_ROWS 8192
#define D      1024
#define WARPS_PER_BLOCK 8
#define NUM_BLOCKS (N_ROWS / WARPS_PER_BLOCK)  // 1024
#define BLOCK_THREADS (WARPS_PER_BLOCK * 32)   // 256

// Per-block partial sums of -log((cos+1)/2). Every slot is rewritten on every
// call before being read, so no reset pass is needed.
__device__ float g_partials[NUM_BLOCKS];
// Arrival counter for the last-block-done pattern. Starts at 0 (static init)
// and is reset to 0 by the last block each call -> graph-replay safe.
__device__ unsigned int g_counter = 0;

// FINAL (rounds 1-13): this shape — LDG.128, 1 row/warp, 256-thread blocks,
// 32 regs, grid 1024 — is the measured optimum at ~6.0 TB/s effective, the
// path-independent chip byte/cycle ceiling for the mandatory 64 MB of reads.
// Tested and rejected: 256-bit loads (R3, R7), 2 warps/row (R4), higher reg
// budget (R5), L2 evict_last (R7), TMA bulk-copy pipelines shallow and deep
// (R8/R9), half-grid persistent (R11), full-occupancy 1184-block grid (R12).
// All regressed or tied. Timed history of this exact source: 10.688, 10.688,
// 11.04, 10.88 us (bench noise ~±0.35 us).
__global__ __launch_bounds__(BLOCK_THREADS)
void row_loss_fused_kernel(const float* __restrict__ x,
                           const float* __restrict__ y,
                           float* __restrict__ out) {
    const int warp = threadIdx.x >> 5;
    const int lane = threadIdx.x & 31;
    const int row  = blockIdx.x * WARPS_PER_BLOCK + warp;

    const float4* __restrict__ xr =
        reinterpret_cast<const float4*>(x + (size_t)row * D);
    const float4* __restrict__ yr =
        reinterpret_cast<const float4*>(y + (size_t)row * D);

    float dot = 0.0f, xx = 0.0f, yy = 0.0f;

    // 1024 floats/row = 256 float4. Lane l reads float4 indices l, l+32, ...
    // -> contiguous 512B warp bursts, 16 independent 16B loads per thread.
    #pragma unroll
    for (int k = 0; k < 8; k++) {
        float4 a = xr[lane + 32 * k];
        float4 b = yr[lane + 32 * k];
        dot += a.x * b.x + a.y * b.y + a.z * b.z + a.w * b.w;
        xx  += a.x * a.x + a.y * a.y + a.z * a.z + a.w * a.w;
        yy  += b.x * b.x + b.y * b.y + b.z * b.z + b.w * b.w;
    }

    // Warp tree reduction of the three accumulators.
    #pragma unroll
    for (int off = 16; off > 0; off >>= 1) {
        dot += __shfl_down_sync(0xFFFFFFFFu, dot, off);
        xx  += __shfl_down_sync(0xFFFFFFFFu, xx,  off);
        yy  += __shfl_down_sync(0xFFFFFFFFu, yy,  off);
    }

    __shared__ float s_loss[WARPS_PER_BLOCK];
    if (lane == 0) {
        float inv_norm = rsqrtf(fmaxf(xx * yy, 1e-24f));
        float cosv = dot * inv_norm;
        float arg  = fmaxf((cosv + 1.0f) * 0.5f, 1e-30f);
        s_loss[warp] = -logf(arg);
    }
    __syncthreads();

    __shared__ bool s_is_last;
    if (threadIdx.x == 0) {
        float t = 0.0f;
        #pragma unroll
        for (int i = 0; i < WARPS_PER_BLOCK; i++) t += s_loss[i];
        g_partials[blockIdx.x] = t;
        // Make the partial visible device-wide before signaling arrival.
        __threadfence();
        unsigned int prev = atomicAdd(&g_counter, 1u);
        s_is_last = (prev == (unsigned int)(NUM_BLOCKS - 1));
    }
    __syncthreads();

    // The single last-arriving block reduces all partials (fixed read order
    // -> deterministic result) and resets the counter for the next replay.
    if (s_is_last) {
        float v = 0.0f;
        #pragma unroll
        for (int i = 0; i < NUM_BLOCKS / BLOCK_THREADS; i++)
            v += g_partials[threadIdx.x + i * BLOCK_THREADS];

        #pragma unroll
        for (int off = 16; off > 0; off >>= 1)
            v += __shfl_down_sync(0xFFFFFFFFu, v, off);

        __shared__ float s_fin[WARPS_PER_BLOCK];
        if (lane == 0) s_fin[warp] = v;
        __syncthreads();

        if (threadIdx.x == 0) {
            float t = 0.0f;
            #pragma unroll
            for (int i = 0; i < WARPS_PER_BLOCK; i++) t += s_fin[i];
            out[0] = t * (1.0f / (float)N_ROWS);
            g_counter = 0;  // re-arm for next graph replay
        }
    }
}

extern "C" void kernel_launch(void* const* d_in, const int* in_sizes, int n_in,
                              void* d_out, int out_size) {
    const float* x = (const float*)d_in[0];
    const float* y = (const float*)d_in[1];
    float* out = (float*)d_out;

    row_loss_fused_kernel<<<NUM_BLOCKS, BLOCK_THREADS>>>(x, y, out);
}